// round 1
// baseline (speedup 1.0000x reference)
#include <cuda_runtime.h>
#include <math.h>

#define N_NODES 10000
#define N_EDGES 640000
#define HD      128
#define NHEADS  8
#define TILE    128
#define SA_STRIDE 132   // 128 + 4 pad: bank = (4*gid + tig) -> conflict-free frags

// scratch (allocation-free rule: __device__ globals)
__device__ float g_Q[N_NODES * HD];
__device__ float g_K[N_NODES * HD];
__device__ float g_V[N_NODES * HD];
__device__ float g_Z[N_NODES * NHEADS];

// smem: sA[128][132] + sB[128][132] + sS[128][8] + sBe[128] + sSrc[128] + sDst[128]
#define SMEM_BYTES ((2 * TILE * SA_STRIDE + TILE * NHEADS + 128) * 4 + 2 * TILE * 4)

__device__ __forceinline__ float cvt_tf32(float x) {
    unsigned u;
    asm("cvt.rna.tf32.f32 %0, %1;" : "=r"(u) : "f"(x));
    return __uint_as_float(u);
}

__device__ __forceinline__ void mma_tf32(float c[4],
                                         unsigned a0, unsigned a1, unsigned a2, unsigned a3,
                                         unsigned b0, unsigned b1) {
    asm volatile(
        "mma.sync.aligned.m16n8k8.row.col.f32.tf32.tf32.f32 "
        "{%0,%1,%2,%3}, {%4,%5,%6,%7}, {%8,%9}, {%0,%1,%2,%3};"
        : "+f"(c[0]), "+f"(c[1]), "+f"(c[2]), "+f"(c[3])
        : "r"(a0), "r"(a1), "r"(a2), "r"(a3), "r"(b0), "r"(b1));
}

// Load a [rows<=128] x 128 fp32 tile (row-major) into smem [128][SA_STRIDE],
// rounding to tf32. Rows >= `rows` are zero-filled.
__device__ __forceinline__ void load_tile_tf32(float* dst, const float* __restrict__ src,
                                               int rows, int tid) {
    for (int idx = tid; idx < TILE * 32; idx += 256) {
        int row = idx >> 5, q = idx & 31;
        float4 v = make_float4(0.f, 0.f, 0.f, 0.f);
        if (row < rows) v = ((const float4*)(src + (size_t)row * 128))[q];
        float4 o = make_float4(cvt_tf32(v.x), cvt_tf32(v.y), cvt_tf32(v.z), cvt_tf32(v.w));
        *((float4*)(dst + row * SA_STRIDE + q * 4)) = o;
    }
}

// 128x128x128 tf32 GEMM on smem tiles. 8 warps: warp_m = wid&3 (32 rows each),
// warp_n = wid>>2 (64 cols each). Each warp: 2 m-tiles x 8 n-tiles of m16n8k8.
__device__ __forceinline__ void gemm_tile(const float* __restrict__ sA,
                                          const float* __restrict__ sB,
                                          float acc[2][8][4],
                                          int lane, int warp_m, int warp_n) {
    int gid = lane >> 2, tig = lane & 3;
#pragma unroll
    for (int kk = 0; kk < 16; kk++) {
        int k0 = kk * 8;
        unsigned a[2][4];
#pragma unroll
        for (int mt = 0; mt < 2; mt++) {
            int r = warp_m * 32 + mt * 16 + gid;
            a[mt][0] = __float_as_uint(sA[r * SA_STRIDE + k0 + tig]);
            a[mt][1] = __float_as_uint(sA[(r + 8) * SA_STRIDE + k0 + tig]);
            a[mt][2] = __float_as_uint(sA[r * SA_STRIDE + k0 + tig + 4]);
            a[mt][3] = __float_as_uint(sA[(r + 8) * SA_STRIDE + k0 + tig + 4]);
        }
#pragma unroll
        for (int nt = 0; nt < 8; nt++) {
            int c = warp_n * 64 + nt * 8 + gid;
            unsigned b0 = __float_as_uint(sB[c * SA_STRIDE + k0 + tig]);
            unsigned b1 = __float_as_uint(sB[c * SA_STRIDE + k0 + tig + 4]);
            mma_tf32(acc[0][nt], a[0][0], a[0][1], a[0][2], a[0][3], b0, b1);
            mma_tf32(acc[1][nt], a[1][0], a[1][1], a[1][2], a[1][3], b0, b1);
        }
    }
}

// ---------------- kernel 0: zero output + z accumulators ----------------
__global__ void k_zero(float* __restrict__ out) {
    int i = blockIdx.x * blockDim.x + threadIdx.x;
    const int n_out4 = N_NODES * HD / 4;      // 320000
    const int n_z4 = N_NODES * NHEADS / 4;    // 20000
    float4 z = make_float4(0.f, 0.f, 0.f, 0.f);
    if (i < n_out4) ((float4*)out)[i] = z;
    else if (i < n_out4 + n_z4) ((float4*)g_Z)[i - n_out4] = z;
}

// ---------------- kernel 1: QKV projections -----------------------------
__global__ void __launch_bounds__(256, 1)
k_proj(const float* __restrict__ h,
       const float* __restrict__ Wq, const float* __restrict__ bq,
       const float* __restrict__ Wk, const float* __restrict__ bk,
       const float* __restrict__ Wv, const float* __restrict__ bv) {
    extern __shared__ float smem[];
    float* sA = smem;
    float* sB = sA + TILE * SA_STRIDE;
    float* sBias = sB + TILE * SA_STRIDE;

    const float* W; const float* b; float* outp;
    if (blockIdx.y == 0)      { W = Wq; b = bq; outp = g_Q; }
    else if (blockIdx.y == 1) { W = Wk; b = bk; outp = g_K; }
    else                      { W = Wv; b = bv; outp = g_V; }

    int tid = threadIdx.x;
    int lane = tid & 31, wid = tid >> 5;
    int warp_m = wid & 3, warp_n = wid >> 2;
    int node0 = blockIdx.x * TILE;
    int rows = N_NODES - node0; if (rows > TILE) rows = TILE;

    if (tid < 128) sBias[tid] = b[tid];
    load_tile_tf32(sA, h + (size_t)node0 * 128, rows, tid);
    load_tile_tf32(sB, W, 128, tid);
    __syncthreads();

    float acc[2][8][4];
#pragma unroll
    for (int mt = 0; mt < 2; mt++)
#pragma unroll
        for (int nt = 0; nt < 8; nt++)
#pragma unroll
            for (int i = 0; i < 4; i++) acc[mt][nt][i] = 0.f;

    gemm_tile(sA, sB, acc, lane, warp_m, warp_n);

    int gid = lane >> 2, tig = lane & 3;
#pragma unroll
    for (int nt = 0; nt < 8; nt++) {
        int c = warp_n * 64 + nt * 8 + 2 * tig;
        float b0 = sBias[c], b1 = sBias[c + 1];
#pragma unroll
        for (int mt = 0; mt < 2; mt++) {
            int r0 = warp_m * 32 + mt * 16 + gid;
            if (r0 < rows)
                *((float2*)(outp + (size_t)(node0 + r0) * 128 + c)) =
                    make_float2(acc[mt][nt][0] + b0, acc[mt][nt][1] + b1);
            int r1 = r0 + 8;
            if (r1 < rows)
                *((float2*)(outp + (size_t)(node0 + r1) * 128 + c)) =
                    make_float2(acc[mt][nt][2] + b0, acc[mt][nt][3] + b1);
        }
    }
}

// ---------------- kernel 2: fused edge kernel ----------------------------
__global__ void __launch_bounds__(256, 1)
k_edge(const float* __restrict__ e, const int* __restrict__ src, const int* __restrict__ dst,
       const float* __restrict__ We, const float* __restrict__ be, float* __restrict__ out) {
    extern __shared__ float smem[];
    float* sA = smem;                          // e tile -> later KQ tile
    float* sB = sA + TILE * SA_STRIDE;         // We
    float* sS = sB + TILE * SA_STRIDE;         // [128][8] edge-head weights
    float* sBe = sS + TILE * NHEADS;           // [128]
    int* sSrc = (int*)(sBe + 128);
    int* sDst = sSrc + TILE;

    int tid = threadIdx.x;
    int lane = tid & 31, wid = tid >> 5;
    int warp_m = wid & 3, warp_n = wid >> 2;
    int edge0 = blockIdx.x * TILE;

    if (tid < 128) {
        sSrc[tid] = src[edge0 + tid];
        sDst[tid] = dst[edge0 + tid];
        sBe[tid] = be[tid];
    }
    load_tile_tf32(sA, e + (size_t)edge0 * 128, 128, tid);
    load_tile_tf32(sB, We, 128, tid);
    __syncthreads();

    float acc[2][8][4];
#pragma unroll
    for (int mt = 0; mt < 2; mt++)
#pragma unroll
        for (int nt = 0; nt < 8; nt++)
#pragma unroll
            for (int i = 0; i < 4; i++) acc[mt][nt][i] = 0.f;

    gemm_tile(sA, sB, acc, lane, warp_m, warp_n);  // acc = E_e (pre-bias)
    __syncthreads();

    // overwrite sA with KQ[i][k] = K[src,k]*Q[dst,k]/sqrt(16)
    for (int idx = tid; idx < TILE * 32; idx += 256) {
        int row = idx >> 5, q = idx & 31;
        int sN = sSrc[row], dN = sDst[row];
        float4 kv = ((const float4*)(g_K + (size_t)sN * 128))[q];
        float4 qv = ((const float4*)(g_Q + (size_t)dN * 128))[q];
        float4 p = make_float4(kv.x * qv.x * 0.25f, kv.y * qv.y * 0.25f,
                               kv.z * qv.z * 0.25f, kv.w * qv.w * 0.25f);
        *((float4*)(sA + row * SA_STRIDE + q * 4)) = p;
    }
    __syncthreads();

    // partial per-head scores: score[e,h] = sum_d KQ * (E + be)
    int gid = lane >> 2, tig = lane & 3;
    float part[2][2][4];
#pragma unroll
    for (int mt = 0; mt < 2; mt++)
#pragma unroll
        for (int rh = 0; rh < 2; rh++)
#pragma unroll
            for (int hg = 0; hg < 4; hg++) part[mt][rh][hg] = 0.f;

#pragma unroll
    for (int nt = 0; nt < 8; nt++) {
        int hg = nt >> 1;
        int c = warp_n * 64 + nt * 8 + 2 * tig;
        float b0 = sBe[c], b1 = sBe[c + 1];
#pragma unroll
        for (int mt = 0; mt < 2; mt++) {
            int r0 = warp_m * 32 + mt * 16 + gid;
            part[mt][0][hg] += (acc[mt][nt][0] + b0) * sA[r0 * SA_STRIDE + c]
                             + (acc[mt][nt][1] + b1) * sA[r0 * SA_STRIDE + c + 1];
            part[mt][1][hg] += (acc[mt][nt][2] + b0) * sA[(r0 + 8) * SA_STRIDE + c]
                             + (acc[mt][nt][3] + b1) * sA[(r0 + 8) * SA_STRIDE + c + 1];
        }
    }

    // reduce across the quad (tig 0..3 hold the 16 dims of each head)
#pragma unroll
    for (int mt = 0; mt < 2; mt++)
#pragma unroll
        for (int rh = 0; rh < 2; rh++)
#pragma unroll
            for (int hg = 0; hg < 4; hg++) {
                float p = part[mt][rh][hg];
                p += __shfl_xor_sync(0xffffffffu, p, 1);
                p += __shfl_xor_sync(0xffffffffu, p, 2);
                if (tig == 0) {
                    int row = warp_m * 32 + mt * 16 + rh * 8 + gid;
                    int head = warp_n * 4 + hg;
                    float sv = expf(fminf(fmaxf(p, -5.f), 5.f));
                    sS[row * NHEADS + head] = sv;
                    atomicAdd(&g_Z[(size_t)sDst[row] * NHEADS + head], sv);
                }
            }
    __syncthreads();

    // scatter: out[dst] += s * V[src]  (128-bit vector atomics, sm_90+)
    for (int idx = tid; idx < TILE * 32; idx += 256) {
        int row = idx >> 5, q = idx & 31;
        int sN = sSrc[row], dN = sDst[row];
        float sc = sS[row * NHEADS + (q >> 2)];
        float4 v = ((const float4*)(g_V + (size_t)sN * 128))[q];
        float4 r = make_float4(v.x * sc, v.y * sc, v.z * sc, v.w * sc);
        atomicAdd((float4*)(out + (size_t)dN * 128 + q * 4), r);
    }
}

// ---------------- kernel 3: normalize -----------------------------------
__global__ void k_final(float* __restrict__ out) {
    int i = blockIdx.x * blockDim.x + threadIdx.x;  // float4 index
    if (i >= N_NODES * HD / 4) return;
    int node = i >> 5;
    int head = (i & 31) >> 2;
    float z = 1.0f / (g_Z[node * NHEADS + head] + 1e-6f);
    float4 v = ((float4*)out)[i];
    v.x *= z; v.y *= z; v.z *= z; v.w *= z;
    ((float4*)out)[i] = v;
}

// ---------------- launcher ------------------------------------------------
extern "C" void kernel_launch(void* const* d_in, const int* in_sizes, int n_in,
                              void* d_out, int out_size) {
    (void)in_sizes; (void)n_in; (void)out_size;
    const float* h  = (const float*)d_in[0];
    const float* e  = (const float*)d_in[1];
    const int*   src = (const int*)d_in[2];
    const int*   dst = (const int*)d_in[3];
    const float* Wq = (const float*)d_in[4];
    const float* bq = (const float*)d_in[5];
    const float* Wk = (const float*)d_in[6];
    const float* bk = (const float*)d_in[7];
    const float* We = (const float*)d_in[8];
    const float* be = (const float*)d_in[9];
    const float* Wv = (const float*)d_in[10];
    const float* bv = (const float*)d_in[11];
    float* out = (float*)d_out;

    cudaFuncSetAttribute(k_proj, cudaFuncAttributeMaxDynamicSharedMemorySize, SMEM_BYTES);
    cudaFuncSetAttribute(k_edge, cudaFuncAttributeMaxDynamicSharedMemorySize, SMEM_BYTES);

    k_zero<<<(N_NODES * HD / 4 + N_NODES * NHEADS / 4 + 255) / 256, 256>>>(out);
    k_proj<<<dim3((N_NODES + TILE - 1) / TILE, 3), 256, SMEM_BYTES>>>(h, Wq, bq, Wk, bk, Wv, bv);
    k_edge<<<N_EDGES / TILE, 256, SMEM_BYTES>>>(e, src, dst, We, be, out);
    k_final<<<(N_NODES * HD / 4 + 255) / 256, 256>>>(out);
}

// round 2
// speedup vs baseline: 1.6186x; 1.6186x over previous
#include <cuda_runtime.h>
#include <math.h>

#define N_NODES 10000
#define N_EDGES 640000
#define HD      128
#define NHEADS  8
#define TILE    128
#define SA_STRIDE 132   // 128 + 4 pad -> conflict-free mma fragment LDS

// scratch (allocation-free rule: __device__ globals)
__device__ float g_Q[N_NODES * HD];
__device__ float g_K[N_NODES * HD];
__device__ float g_V[N_NODES * HD];
__device__ float g_Z[N_NODES * NHEADS];

// edge kernel smem: sE + sW + sKQ (each 128x132 f32) + sS[128][8] + sBe[128] + idx
#define SMEM_EDGE  ((3 * TILE * SA_STRIDE + TILE * NHEADS + 128) * 4 + 2 * TILE * 4)
// proj kernel smem: sA + sB + bias
#define SMEM_PROJ  ((2 * TILE * SA_STRIDE + 128) * 4)

__device__ __forceinline__ float cvt_tf32(float x) {
    unsigned u;
    asm("cvt.rna.tf32.f32 %0, %1;" : "=r"(u) : "f"(x));
    return __uint_as_float(u);
}

__device__ __forceinline__ void mma_tf32(float c[4],
                                         unsigned a0, unsigned a1, unsigned a2, unsigned a3,
                                         unsigned b0, unsigned b1) {
    asm volatile(
        "mma.sync.aligned.m16n8k8.row.col.f32.tf32.tf32.f32 "
        "{%0,%1,%2,%3}, {%4,%5,%6,%7}, {%8,%9}, {%0,%1,%2,%3};"
        : "+f"(c[0]), "+f"(c[1]), "+f"(c[2]), "+f"(c[3])
        : "r"(a0), "r"(a1), "r"(a2), "r"(a3), "r"(b0), "r"(b1));
}

// Load a [rows<=128] x 128 fp32 tile into smem [128][SA_STRIDE], tf32-rounded.
// NT = threads in block.
template <int NT>
__device__ __forceinline__ void load_tile_tf32(float* dst, const float* __restrict__ src,
                                               int rows, int tid) {
    for (int idx = tid; idx < TILE * 32; idx += NT) {
        int row = idx >> 5, q = idx & 31;
        float4 v = make_float4(0.f, 0.f, 0.f, 0.f);
        if (row < rows) v = ((const float4*)(src + (size_t)row * 128))[q];
        float4 o = make_float4(cvt_tf32(v.x), cvt_tf32(v.y), cvt_tf32(v.z), cvt_tf32(v.w));
        *((float4*)(dst + row * SA_STRIDE + q * 4)) = o;
    }
}

// 128x128x128 tf32 GEMM on smem tiles. 16 warps: warp_m = wid&3 (32 rows),
// warp_n = wid>>2 (32 cols). Each warp: 2 m-tiles x 4 n-tiles of m16n8k8.
__device__ __forceinline__ void gemm_tile16(const float* __restrict__ sA,
                                            const float* __restrict__ sB,
                                            float acc[2][4][4],
                                            int lane, int warp_m, int warp_n) {
    int gid = lane >> 2, tig = lane & 3;
#pragma unroll
    for (int kk = 0; kk < 16; kk++) {
        int k0 = kk * 8;
        unsigned a[2][4];
#pragma unroll
        for (int mt = 0; mt < 2; mt++) {
            int r = warp_m * 32 + mt * 16 + gid;
            a[mt][0] = __float_as_uint(sA[r * SA_STRIDE + k0 + tig]);
            a[mt][1] = __float_as_uint(sA[(r + 8) * SA_STRIDE + k0 + tig]);
            a[mt][2] = __float_as_uint(sA[r * SA_STRIDE + k0 + tig + 4]);
            a[mt][3] = __float_as_uint(sA[(r + 8) * SA_STRIDE + k0 + tig + 4]);
        }
#pragma unroll
        for (int nt = 0; nt < 4; nt++) {
            int c = warp_n * 32 + nt * 8 + gid;
            unsigned b0 = __float_as_uint(sB[c * SA_STRIDE + k0 + tig]);
            unsigned b1 = __float_as_uint(sB[c * SA_STRIDE + k0 + tig + 4]);
            mma_tf32(acc[0][nt], a[0][0], a[0][1], a[0][2], a[0][3], b0, b1);
            mma_tf32(acc[1][nt], a[1][0], a[1][1], a[1][2], a[1][3], b0, b1);
        }
    }
}

// ---------------- kernel 0: zero output + z accumulators ----------------
__global__ void k_zero(float* __restrict__ out) {
    int i = blockIdx.x * blockDim.x + threadIdx.x;
    const int n_out4 = N_NODES * HD / 4;
    const int n_z4 = N_NODES * NHEADS / 4;
    float4 z = make_float4(0.f, 0.f, 0.f, 0.f);
    if (i < n_out4) ((float4*)out)[i] = z;
    else if (i < n_out4 + n_z4) ((float4*)g_Z)[i - n_out4] = z;
}

// ---------------- kernel 1: QKV projections -----------------------------
__global__ void __launch_bounds__(512, 1)
k_proj(const float* __restrict__ h,
       const float* __restrict__ Wq, const float* __restrict__ bq,
       const float* __restrict__ Wk, const float* __restrict__ bk,
       const float* __restrict__ Wv, const float* __restrict__ bv) {
    extern __shared__ float smem[];
    float* sA = smem;
    float* sB = sA + TILE * SA_STRIDE;
    float* sBias = sB + TILE * SA_STRIDE;

    const float* W; const float* b; float* outp;
    if (blockIdx.y == 0)      { W = Wq; b = bq; outp = g_Q; }
    else if (blockIdx.y == 1) { W = Wk; b = bk; outp = g_K; }
    else                      { W = Wv; b = bv; outp = g_V; }

    int tid = threadIdx.x;
    int lane = tid & 31, wid = tid >> 5;
    int warp_m = wid & 3, warp_n = wid >> 2;
    int node0 = blockIdx.x * TILE;
    int rows = N_NODES - node0; if (rows > TILE) rows = TILE;

    if (tid < 128) sBias[tid] = b[tid];
    load_tile_tf32<512>(sA, h + (size_t)node0 * 128, rows, tid);
    load_tile_tf32<512>(sB, W, 128, tid);
    __syncthreads();

    float acc[2][4][4];
#pragma unroll
    for (int mt = 0; mt < 2; mt++)
#pragma unroll
        for (int nt = 0; nt < 4; nt++)
#pragma unroll
            for (int i = 0; i < 4; i++) acc[mt][nt][i] = 0.f;

    gemm_tile16(sA, sB, acc, lane, warp_m, warp_n);

    int gid = lane >> 2, tig = lane & 3;
#pragma unroll
    for (int nt = 0; nt < 4; nt++) {
        int c = warp_n * 32 + nt * 8 + 2 * tig;
        float b0 = sBias[c], b1 = sBias[c + 1];
#pragma unroll
        for (int mt = 0; mt < 2; mt++) {
            int r0 = warp_m * 32 + mt * 16 + gid;
            if (r0 < rows)
                *((float2*)(outp + (size_t)(node0 + r0) * 128 + c)) =
                    make_float2(acc[mt][nt][0] + b0, acc[mt][nt][1] + b1);
            int r1 = r0 + 8;
            if (r1 < rows)
                *((float2*)(outp + (size_t)(node0 + r1) * 128 + c)) =
                    make_float2(acc[mt][nt][2] + b0, acc[mt][nt][3] + b1);
        }
    }
}

// ---------------- kernel 2: fused edge kernel ----------------------------
__global__ void __launch_bounds__(512, 1)
k_edge(const float* __restrict__ e, const int* __restrict__ src, const int* __restrict__ dst,
       const float* __restrict__ We, const float* __restrict__ be, float* __restrict__ out) {
    extern __shared__ float smem[];
    float* sE  = smem;                          // e tile (tf32)
    float* sW  = sE + TILE * SA_STRIDE;         // We (tf32)
    float* sKQ = sW + TILE * SA_STRIDE;         // K[src]*Q[dst]/sqrt(D) (fp32)
    float* sS  = sKQ + TILE * SA_STRIDE;        // [128][8] edge-head weights
    float* sBe = sS + TILE * NHEADS;            // [128]
    int* sSrc = (int*)(sBe + 128);
    int* sDst = sSrc + TILE;

    int tid = threadIdx.x;
    int lane = tid & 31, wid = tid >> 5;
    int warp_m = wid & 3, warp_n = wid >> 2;
    int edge0 = blockIdx.x * TILE;

    if (tid < 128) {
        sSrc[tid] = src[edge0 + tid];
        sDst[tid] = dst[edge0 + tid];
        sBe[tid] = be[tid];
    }
    load_tile_tf32<512>(sE, e + (size_t)edge0 * 128, 128, tid);
    load_tile_tf32<512>(sW, We, 128, tid);
    __syncthreads();   // idx + tiles visible

    // gather phase: sKQ[i][k] = K[src,k]*Q[dst,k]/sqrt(16); issued before GEMM
    // so the L2 gather latency hides under the tensor work of other warps.
#pragma unroll
    for (int it = 0; it < (TILE * 32) / 512; it++) {
        int idx = tid + it * 512;
        int row = idx >> 5, q = idx & 31;
        int sN = sSrc[row], dN = sDst[row];
        float4 kv = ((const float4*)(g_K + (size_t)sN * 128))[q];
        float4 qv = ((const float4*)(g_Q + (size_t)dN * 128))[q];
        float4 p = make_float4(kv.x * qv.x * 0.25f, kv.y * qv.y * 0.25f,
                               kv.z * qv.z * 0.25f, kv.w * qv.w * 0.25f);
        *((float4*)(sKQ + row * SA_STRIDE + q * 4)) = p;
    }

    float acc[2][4][4];
#pragma unroll
    for (int mt = 0; mt < 2; mt++)
#pragma unroll
        for (int nt = 0; nt < 4; nt++)
#pragma unroll
            for (int i = 0; i < 4; i++) acc[mt][nt][i] = 0.f;

    gemm_tile16(sE, sW, acc, lane, warp_m, warp_n);   // acc = E_e (pre-bias)
    __syncthreads();   // all gathers + GEMM done; sKQ fully written

    // partial per-head scores: score[e,h] = sum_d KQ * (E + be)
    int gid = lane >> 2, tig = lane & 3;
    float part[2][2][2];
#pragma unroll
    for (int mt = 0; mt < 2; mt++)
#pragma unroll
        for (int rh = 0; rh < 2; rh++)
#pragma unroll
            for (int hg = 0; hg < 2; hg++) part[mt][rh][hg] = 0.f;

#pragma unroll
    for (int nt = 0; nt < 4; nt++) {
        int hg = nt >> 1;
        int c = warp_n * 32 + nt * 8 + 2 * tig;
        float b0 = sBe[c], b1 = sBe[c + 1];
#pragma unroll
        for (int mt = 0; mt < 2; mt++) {
            int r0 = warp_m * 32 + mt * 16 + gid;
            part[mt][0][hg] += (acc[mt][nt][0] + b0) * sKQ[r0 * SA_STRIDE + c]
                             + (acc[mt][nt][1] + b1) * sKQ[r0 * SA_STRIDE + c + 1];
            part[mt][1][hg] += (acc[mt][nt][2] + b0) * sKQ[(r0 + 8) * SA_STRIDE + c]
                             + (acc[mt][nt][3] + b1) * sKQ[(r0 + 8) * SA_STRIDE + c + 1];
        }
    }

    // reduce across the quad (tig 0..3 hold the 16 dims of each head)
#pragma unroll
    for (int mt = 0; mt < 2; mt++)
#pragma unroll
        for (int rh = 0; rh < 2; rh++)
#pragma unroll
            for (int hg = 0; hg < 2; hg++) {
                float p = part[mt][rh][hg];
                p += __shfl_xor_sync(0xffffffffu, p, 1);
                p += __shfl_xor_sync(0xffffffffu, p, 2);
                if (tig == 0) {
                    int row = warp_m * 32 + mt * 16 + rh * 8 + gid;
                    int head = warp_n * 2 + hg;
                    float sv = expf(fminf(fmaxf(p, -5.f), 5.f));
                    sS[row * NHEADS + head] = sv;
                    atomicAdd(&g_Z[(size_t)sDst[row] * NHEADS + head], sv);
                }
            }
    __syncthreads();

    // scatter: out[dst] += s * V[src]  (128-bit vector atomics)
#pragma unroll
    for (int it = 0; it < (TILE * 32) / 512; it++) {
        int idx = tid + it * 512;
        int row = idx >> 5, q = idx & 31;
        int sN = sSrc[row], dN = sDst[row];
        float sc = sS[row * NHEADS + (q >> 2)];
        float4 v = ((const float4*)(g_V + (size_t)sN * 128))[q];
        float4 r = make_float4(v.x * sc, v.y * sc, v.z * sc, v.w * sc);
        atomicAdd((float4*)(out + (size_t)dN * 128 + q * 4), r);
    }
}

// ---------------- kernel 3: normalize -----------------------------------
__global__ void k_final(float* __restrict__ out) {
    int i = blockIdx.x * blockDim.x + threadIdx.x;  // float4 index
    if (i >= N_NODES * HD / 4) return;
    int node = i >> 5;
    int head = (i & 31) >> 2;
    float z = 1.0f / (g_Z[node * NHEADS + head] + 1e-6f);
    float4 v = ((float4*)out)[i];
    v.x *= z; v.y *= z; v.z *= z; v.w *= z;
    ((float4*)out)[i] = v;
}

// ---------------- launcher ------------------------------------------------
extern "C" void kernel_launch(void* const* d_in, const int* in_sizes, int n_in,
                              void* d_out, int out_size) {
    (void)in_sizes; (void)n_in; (void)out_size;
    const float* h  = (const float*)d_in[0];
    const float* e  = (const float*)d_in[1];
    const int*   src = (const int*)d_in[2];
    const int*   dst = (const int*)d_in[3];
    const float* Wq = (const float*)d_in[4];
    const float* bq = (const float*)d_in[5];
    const float* Wk = (const float*)d_in[6];
    const float* bk = (const float*)d_in[7];
    const float* We = (const float*)d_in[8];
    const float* be = (const float*)d_in[9];
    const float* Wv = (const float*)d_in[10];
    const float* bv = (const float*)d_in[11];
    float* out = (float*)d_out;

    cudaFuncSetAttribute(k_proj, cudaFuncAttributeMaxDynamicSharedMemorySize, SMEM_PROJ);
    cudaFuncSetAttribute(k_edge, cudaFuncAttributeMaxDynamicSharedMemorySize, SMEM_EDGE);

    k_zero<<<(N_NODES * HD / 4 + N_NODES * NHEADS / 4 + 255) / 256, 256>>>(out);
    k_proj<<<dim3((N_NODES + TILE - 1) / TILE, 3), 512, SMEM_PROJ>>>(h, Wq, bq, Wk, bk, Wv, bv);
    k_edge<<<N_EDGES / TILE, 512, SMEM_EDGE>>>(e, src, dst, We, be, out);
    k_final<<<(N_NODES * HD / 4 + 255) / 256, 256>>>(out);
}

// round 3
// speedup vs baseline: 2.1877x; 1.3516x over previous
#include <cuda_runtime.h>
#include <math.h>

#define N_NODES 10000
#define N_EDGES 640000
#define HD      128
#define NHEADS  8
#define TILE    128
#define NTILES  (N_EDGES / TILE)   // 5000
#define SA_STRIDE 132              // 128 + 4 pad -> conflict-free mma fragment LDS
#define EDGE_GRID 148

// scratch (allocation-free rule: __device__ globals)
__device__ float g_Q[N_NODES * HD];
__device__ float g_K[N_NODES * HD];
__device__ float g_V[N_NODES * HD];
__device__ float g_Z[N_NODES * NHEADS];

// edge kernel smem: sE0 + sE1 + sW (each 128x132 f32) + sS[128][8] + sBe[128] + idx[4][256]
#define SMEM_EDGE  ((3 * TILE * SA_STRIDE + TILE * NHEADS + 128) * 4 + 4 * 256 * 4)
// proj kernel smem: sA + sB + bias
#define SMEM_PROJ  ((2 * TILE * SA_STRIDE + 128) * 4)

__device__ __forceinline__ float cvt_tf32(float x) {
    unsigned u;
    asm("cvt.rna.tf32.f32 %0, %1;" : "=r"(u) : "f"(x));
    return __uint_as_float(u);
}

__device__ __forceinline__ void mma_tf32(float c[4],
                                         unsigned a0, unsigned a1, unsigned a2, unsigned a3,
                                         unsigned b0, unsigned b1) {
    asm volatile(
        "mma.sync.aligned.m16n8k8.row.col.f32.tf32.tf32.f32 "
        "{%0,%1,%2,%3}, {%4,%5,%6,%7}, {%8,%9}, {%0,%1,%2,%3};"
        : "+f"(c[0]), "+f"(c[1]), "+f"(c[2]), "+f"(c[3])
        : "r"(a0), "r"(a1), "r"(a2), "r"(a3), "r"(b0), "r"(b1));
}

// fp32 tile -> smem, tf32-rounded (for W operands)
template <int NT>
__device__ __forceinline__ void load_tile_tf32(float* dst, const float* __restrict__ src,
                                               int rows, int tid) {
    for (int idx = tid; idx < TILE * 32; idx += NT) {
        int row = idx >> 5, q = idx & 31;
        float4 v = make_float4(0.f, 0.f, 0.f, 0.f);
        if (row < rows) v = ((const float4*)(src + (size_t)row * 128))[q];
        float4 o = make_float4(cvt_tf32(v.x), cvt_tf32(v.y), cvt_tf32(v.z), cvt_tf32(v.w));
        *((float4*)(dst + row * SA_STRIDE + q * 4)) = o;
    }
}

// async raw-fp32 tile prefetch into [128][SA_STRIDE] smem
__device__ __forceinline__ void cp_async_tile(float* sDst, const float* __restrict__ gSrc,
                                              int tid) {
#pragma unroll
    for (int it = 0; it < 8; it++) {
        int idx = tid + it * 512;
        int row = idx >> 5, q = idx & 31;
        unsigned saddr = (unsigned)__cvta_generic_to_shared(sDst + row * SA_STRIDE + q * 4);
        asm volatile("cp.async.cg.shared.global [%0], [%1], 16;\n"
                     :: "r"(saddr), "l"(gSrc + (size_t)row * 128 + q * 4));
    }
}

// 128x128x128 tf32 GEMM; A raw fp32 in smem (cvt in regs), B tf32 in smem.
// 16 warps: warp_m = wid&3 (32 rows), warp_n = wid>>2 (32 cols).
template <bool CVT_A>
__device__ __forceinline__ void gemm_tile16(const float* __restrict__ sA,
                                            const float* __restrict__ sB,
                                            float acc[2][4][4],
                                            int lane, int warp_m, int warp_n) {
    int gid = lane >> 2, tig = lane & 3;
#pragma unroll
    for (int kk = 0; kk < 16; kk++) {
        int k0 = kk * 8;
        unsigned a[2][4];
#pragma unroll
        for (int mt = 0; mt < 2; mt++) {
            int r = warp_m * 32 + mt * 16 + gid;
            float v0 = sA[r * SA_STRIDE + k0 + tig];
            float v1 = sA[(r + 8) * SA_STRIDE + k0 + tig];
            float v2 = sA[r * SA_STRIDE + k0 + tig + 4];
            float v3 = sA[(r + 8) * SA_STRIDE + k0 + tig + 4];
            if (CVT_A) { v0 = cvt_tf32(v0); v1 = cvt_tf32(v1); v2 = cvt_tf32(v2); v3 = cvt_tf32(v3); }
            a[mt][0] = __float_as_uint(v0); a[mt][1] = __float_as_uint(v1);
            a[mt][2] = __float_as_uint(v2); a[mt][3] = __float_as_uint(v3);
        }
#pragma unroll
        for (int nt = 0; nt < 4; nt++) {
            int c = warp_n * 32 + nt * 8 + gid;
            unsigned b0 = __float_as_uint(sB[c * SA_STRIDE + k0 + tig]);
            unsigned b1 = __float_as_uint(sB[c * SA_STRIDE + k0 + tig + 4]);
            mma_tf32(acc[0][nt], a[0][0], a[0][1], a[0][2], a[0][3], b0, b1);
            mma_tf32(acc[1][nt], a[1][0], a[1][1], a[1][2], a[1][3], b0, b1);
        }
    }
}

// ---------------- kernel 0: zero output + z accumulators ----------------
__global__ void k_zero(float* __restrict__ out) {
    int i = blockIdx.x * blockDim.x + threadIdx.x;
    const int n_out4 = N_NODES * HD / 4;
    const int n_z4 = N_NODES * NHEADS / 4;
    float4 z = make_float4(0.f, 0.f, 0.f, 0.f);
    if (i < n_out4) ((float4*)out)[i] = z;
    else if (i < n_out4 + n_z4) ((float4*)g_Z)[i - n_out4] = z;
}

// ---------------- kernel 1: QKV projections -----------------------------
__global__ void __launch_bounds__(512, 1)
k_proj(const float* __restrict__ h,
       const float* __restrict__ Wq, const float* __restrict__ bq,
       const float* __restrict__ Wk, const float* __restrict__ bk,
       const float* __restrict__ Wv, const float* __restrict__ bv) {
    extern __shared__ float smem[];
    float* sA = smem;
    float* sB = sA + TILE * SA_STRIDE;
    float* sBias = sB + TILE * SA_STRIDE;

    const float* W; const float* b; float* outp;
    if (blockIdx.y == 0)      { W = Wq; b = bq; outp = g_Q; }
    else if (blockIdx.y == 1) { W = Wk; b = bk; outp = g_K; }
    else                      { W = Wv; b = bv; outp = g_V; }

    int tid = threadIdx.x;
    int lane = tid & 31, wid = tid >> 5;
    int warp_m = wid & 3, warp_n = wid >> 2;
    int node0 = blockIdx.x * TILE;
    int rows = N_NODES - node0; if (rows > TILE) rows = TILE;

    if (tid < 128) sBias[tid] = b[tid];
    load_tile_tf32<512>(sA, h + (size_t)node0 * 128, rows, tid);
    load_tile_tf32<512>(sB, W, 128, tid);
    __syncthreads();

    float acc[2][4][4];
#pragma unroll
    for (int mt = 0; mt < 2; mt++)
#pragma unroll
        for (int nt = 0; nt < 4; nt++)
#pragma unroll
            for (int i = 0; i < 4; i++) acc[mt][nt][i] = 0.f;

    gemm_tile16<false>(sA, sB, acc, lane, warp_m, warp_n);

    int gid = lane >> 2, tig = lane & 3;
#pragma unroll
    for (int nt = 0; nt < 4; nt++) {
        int c = warp_n * 32 + nt * 8 + 2 * tig;
        float b0 = sBias[c], b1 = sBias[c + 1];
#pragma unroll
        for (int mt = 0; mt < 2; mt++) {
            int r0 = warp_m * 32 + mt * 16 + gid;
            if (r0 < rows)
                *((float2*)(outp + (size_t)(node0 + r0) * 128 + c)) =
                    make_float2(acc[mt][nt][0] + b0, acc[mt][nt][1] + b1);
            int r1 = r0 + 8;
            if (r1 < rows)
                *((float2*)(outp + (size_t)(node0 + r1) * 128 + c)) =
                    make_float2(acc[mt][nt][2] + b0, acc[mt][nt][3] + b1);
        }
    }
}

// ---------------- kernel 2: persistent fused edge kernel -----------------
__global__ void __launch_bounds__(512, 1)
k_edge(const float* __restrict__ e, const int* __restrict__ src, const int* __restrict__ dst,
       const float* __restrict__ We, const float* __restrict__ be, float* __restrict__ out) {
    extern __shared__ float smem[];
    float* sE0 = smem;                          // e tile buf 0 (raw fp32)
    float* sE1 = sE0 + TILE * SA_STRIDE;        // e tile buf 1
    float* sW  = sE1 + TILE * SA_STRIDE;        // We (tf32), resident
    float* sS  = sW + TILE * SA_STRIDE;         // [128][8] edge-head weights
    float* sBe = sS + TILE * NHEADS;            // [128]
    int* sIdx = (int*)(sBe + 128);              // [4][256]: src|dst per slot

    int tid = threadIdx.x;
    int lane = tid & 31, wid = tid >> 5;
    int warp_m = wid & 3, warp_n = wid >> 2;
    int gid = lane >> 2, tig = lane & 3;
    const int stride = gridDim.x;

    // resident operands
    load_tile_tf32<512>(sW, We, 128, tid);
    if (tid < 128) sBe[tid] = be[tid];

    // prologue: prefetch tiles t0, t1
    int t0 = blockIdx.x;
    if (t0 < NTILES) {
        cp_async_tile(sE0, e + (size_t)t0 * TILE * 128, tid);
        if (tid < 128) {
            sIdx[tid] = src[t0 * TILE + tid];
            sIdx[128 + tid] = dst[t0 * TILE + tid];
        }
    }
    asm volatile("cp.async.commit_group;\n" ::: "memory");
    int t1 = t0 + stride;
    if (t1 < NTILES) {
        cp_async_tile(sE1, e + (size_t)t1 * TILE * 128, tid);
        if (tid < 128) {
            sIdx[256 + tid] = src[t1 * TILE + tid];
            sIdx[256 + 128 + tid] = dst[t1 * TILE + tid];
        }
    }
    asm volatile("cp.async.commit_group;\n" ::: "memory");

    int k = 0;
    for (int t = t0; t < NTILES; t += stride, k++) {
        asm volatile("cp.async.wait_group 1;\n" ::: "memory");
        __syncthreads();   // tile t + idx t visible; prev-iter smem readers done

        float* sE = (k & 1) ? sE1 : sE0;
        const int* sSrc = sIdx + (k & 3) * 256;
        const int* sDst = sSrc + 128;

        // gather K[src]*Q[dst]/sqrt(D) straight into mma-fragment registers
        float2 kq[2][2][4];
#pragma unroll
        for (int mt = 0; mt < 2; mt++)
#pragma unroll
            for (int rh = 0; rh < 2; rh++) {
                int r = warp_m * 32 + mt * 16 + rh * 8 + gid;
                const float* Kp = g_K + (size_t)sSrc[r] * 128;
                const float* Qp = g_Q + (size_t)sDst[r] * 128;
#pragma unroll
                for (int nt = 0; nt < 4; nt++) {
                    int c = warp_n * 32 + nt * 8 + 2 * tig;
                    float2 kv = *(const float2*)(Kp + c);
                    float2 qv = *(const float2*)(Qp + c);
                    kq[mt][rh][nt] = make_float2(kv.x * qv.x * 0.25f, kv.y * qv.y * 0.25f);
                }
            }

        float acc[2][4][4];
#pragma unroll
        for (int mt = 0; mt < 2; mt++)
#pragma unroll
            for (int nt = 0; nt < 4; nt++)
#pragma unroll
                for (int i = 0; i < 4; i++) acc[mt][nt][i] = 0.f;

        gemm_tile16<true>(sE, sW, acc, lane, warp_m, warp_n);  // acc = E_e

        // per-head scores: score[e,h] = sum_d KQ * (E + be)
        float part[2][2][2];
#pragma unroll
        for (int mt = 0; mt < 2; mt++)
#pragma unroll
            for (int rh = 0; rh < 2; rh++)
#pragma unroll
                for (int hg = 0; hg < 2; hg++) part[mt][rh][hg] = 0.f;

#pragma unroll
        for (int nt = 0; nt < 4; nt++) {
            int hg = nt >> 1;
            int c = warp_n * 32 + nt * 8 + 2 * tig;
            float b0 = sBe[c], b1 = sBe[c + 1];
#pragma unroll
            for (int mt = 0; mt < 2; mt++) {
                part[mt][0][hg] += (acc[mt][nt][0] + b0) * kq[mt][0][nt].x
                                 + (acc[mt][nt][1] + b1) * kq[mt][0][nt].y;
                part[mt][1][hg] += (acc[mt][nt][2] + b0) * kq[mt][1][nt].x
                                 + (acc[mt][nt][3] + b1) * kq[mt][1][nt].y;
            }
        }

#pragma unroll
        for (int mt = 0; mt < 2; mt++)
#pragma unroll
            for (int rh = 0; rh < 2; rh++)
#pragma unroll
                for (int hg = 0; hg < 2; hg++) {
                    float p = part[mt][rh][hg];
                    p += __shfl_xor_sync(0xffffffffu, p, 1);
                    p += __shfl_xor_sync(0xffffffffu, p, 2);
                    if (tig == 0) {
                        int row = warp_m * 32 + mt * 16 + rh * 8 + gid;
                        int head = warp_n * 2 + hg;
                        float sv = expf(fminf(fmaxf(p, -5.f), 5.f));
                        sS[row * NHEADS + head] = sv;
                        atomicAdd(&g_Z[(size_t)sDst[row] * NHEADS + head], sv);
                    }
                }
        __syncthreads();   // sS published; sE GEMM reads complete

        // prefetch tile t+2 into the buffer just freed
        int t2 = t + 2 * stride;
        if (t2 < NTILES) {
            cp_async_tile(sE, e + (size_t)t2 * TILE * 128, tid);
            if (tid < 128) {
                int* d = sIdx + ((k + 2) & 3) * 256;
                d[tid] = src[t2 * TILE + tid];
                d[128 + tid] = dst[t2 * TILE + tid];
            }
        }
        asm volatile("cp.async.commit_group;\n" ::: "memory");

        // scatter: out[dst] += s * V[src]
#pragma unroll
        for (int it = 0; it < 8; it++) {
            int idx = tid + it * 512;
            int row = idx >> 5, q = idx & 31;
            int sN = sSrc[row], dN = sDst[row];
            float sc = sS[row * NHEADS + (q >> 2)];
            float4 v = ((const float4*)(g_V + (size_t)sN * 128))[q];
            float4 r = make_float4(v.x * sc, v.y * sc, v.z * sc, v.w * sc);
            atomicAdd((float4*)(out + (size_t)dN * 128 + q * 4), r);
        }
    }
}

// ---------------- kernel 3: normalize -----------------------------------
__global__ void k_final(float* __restrict__ out) {
    int i = blockIdx.x * blockDim.x + threadIdx.x;  // float4 index
    if (i >= N_NODES * HD / 4) return;
    int node = i >> 5;
    int head = (i & 31) >> 2;
    float z = 1.0f / (g_Z[node * NHEADS + head] + 1e-6f);
    float4 v = ((float4*)out)[i];
    v.x *= z; v.y *= z; v.z *= z; v.w *= z;
    ((float4*)out)[i] = v;
}

// ---------------- launcher ------------------------------------------------
extern "C" void kernel_launch(void* const* d_in, const int* in_sizes, int n_in,
                              void* d_out, int out_size) {
    (void)in_sizes; (void)n_in; (void)out_size;
    const float* h  = (const float*)d_in[0];
    const float* e  = (const float*)d_in[1];
    const int*   src = (const int*)d_in[2];
    const int*   dst = (const int*)d_in[3];
    const float* Wq = (const float*)d_in[4];
    const float* bq = (const float*)d_in[5];
    const float* Wk = (const float*)d_in[6];
    const float* bk = (const float*)d_in[7];
    const float* We = (const float*)d_in[8];
    const float* be = (const float*)d_in[9];
    const float* Wv = (const float*)d_in[10];
    const float* bv = (const float*)d_in[11];
    float* out = (float*)d_out;

    cudaFuncSetAttribute(k_proj, cudaFuncAttributeMaxDynamicSharedMemorySize, SMEM_PROJ);
    cudaFuncSetAttribute(k_edge, cudaFuncAttributeMaxDynamicSharedMemorySize, SMEM_EDGE);

    k_zero<<<(N_NODES * HD / 4 + N_NODES * NHEADS / 4 + 255) / 256, 256>>>(out);
    k_proj<<<dim3((N_NODES + TILE - 1) / TILE, 3), 512, SMEM_PROJ>>>(h, Wq, bq, Wk, bk, Wv, bv);
    k_edge<<<EDGE_GRID, 512, SMEM_EDGE>>>(e, src, dst, We, be, out);
    k_final<<<(N_NODES * HD / 4 + 255) / 256, 256>>>(out);
}